// round 4
// baseline (speedup 1.0000x reference)
#include <cuda_runtime.h>

#define ROWS          8192
#define BLOCK         256
#define WARPS_PER_CTA (BLOCK / 32)
#define GRID          (ROWS / WARPS_PER_CTA)   // 1024 CTAs -> exactly 1 warp per row

// Allocation-free scratch: accumulator + completion counter.
__device__ float    g_acc   = 0.0f;
__device__ unsigned g_count = 0;

// Persistent single-wave kernel: one WARP per row. Each warp streams its
// 64 KB row with float4 streaming loads, reduces with shuffles (no CTA
// barriers in the hot path), hinges, and accumulates per-warp. One CTA
// reduce + one global atomic per CTA at the end; last CTA writes the mean.
__global__ void __launch_bounds__(BLOCK, 7) bloss_persistent_kernel(
    const float* __restrict__ B, float* __restrict__ out, int cols)
{
    const int lane  = threadIdx.x & 31;
    const int wid   = threadIdx.x >> 5;
    const int gwarp = blockIdx.x * WARPS_PER_CTA + wid;
    const int total_warps = gridDim.x * WARPS_PER_CTA;
    const int n4 = cols >> 2;   // float4 per row (4096 for cols=16384)

    float hinge_acc = 0.0f;

    for (int row = gwarp; row < ROWS; row += total_warps) {
        const float4* __restrict__ p =
            reinterpret_cast<const float4*>(B + (size_t)row * (size_t)cols);

        float s0 = 0.0f, s1 = 0.0f, s2 = 0.0f, s3 = 0.0f;
        int i = lane;
        // 4 independent LDG.128 per iteration at immediate offsets; the warp
        // covers 2 KB per batch. n4=4096 divides 128 evenly -> no tail.
        for (; i + 96 < n4; i += 128) {
            float4 v0 = __ldcs(p + i);
            float4 v1 = __ldcs(p + i + 32);
            float4 v2 = __ldcs(p + i + 64);
            float4 v3 = __ldcs(p + i + 96);
            s0 += (v0.x + v0.y) + (v0.z + v0.w);
            s1 += (v1.x + v1.y) + (v1.z + v1.w);
            s2 += (v2.x + v2.y) + (v2.z + v2.w);
            s3 += (v3.x + v3.y) + (v3.z + v3.w);
        }
        for (; i < n4; i += 32) {
            float4 v = __ldcs(p + i);
            s0 += (v.x + v.y) + (v.z + v.w);
        }
        float s = (s0 + s1) + (s2 + s3);

        // Warp-only reduce: no smem, no syncthreads.
        #pragma unroll
        for (int o = 16; o > 0; o >>= 1)
            s += __shfl_down_sync(0xffffffffu, s, o);

        if (lane == 0)
            hinge_acc += fmaxf(s - 1.0f, 0.0f);
    }

    // One CTA reduce at the very end.
    __shared__ float ws[WARPS_PER_CTA];
    if (lane == 0) ws[wid] = hinge_acc;
    __syncthreads();

    if (threadIdx.x == 0) {
        float t = ws[0];
        #pragma unroll
        for (int w = 1; w < WARPS_PER_CTA; w++) t += ws[w];

        atomicAdd(&g_acc, t);
        __threadfence();
        unsigned done = atomicAdd(&g_count, 1u);
        if (done == (unsigned)gridDim.x - 1u) {
            float total = *(volatile float*)&g_acc;
            out[0] = total / (float)ROWS;
            // Reset for next graph replay.
            *(volatile float*)&g_acc = 0.0f;
            *(volatile unsigned*)&g_count = 0u;
            __threadfence();
        }
    }
}

extern "C" void kernel_launch(void* const* d_in, const int* in_sizes, int n_in,
                              void* d_out, int out_size)
{
    const float* B = (const float*)d_in[0];
    const int rows = ROWS;                   // 8192 per problem spec
    const int cols = in_sizes[0] / rows;     // 16384

    bloss_persistent_kernel<<<GRID, BLOCK>>>(B, (float*)d_out, cols);
}

// round 5
// speedup vs baseline: 1.1559x; 1.1559x over previous
#include <cuda_runtime.h>

#define ROWS  8192
#define COLS  16384
#define BLOCK 512

// Allocation-free scratch: accumulator + completion counter.
__device__ float    g_acc   = 0.0f;
__device__ unsigned g_count = 0;

__device__ __forceinline__ void epilogue(float s, float* __restrict__ out)
{
    // Warp reduce
    #pragma unroll
    for (int o = 16; o > 0; o >>= 1)
        s += __shfl_down_sync(0xffffffffu, s, o);

    __shared__ float ws[BLOCK / 32];
    if ((threadIdx.x & 31) == 0) ws[threadIdx.x >> 5] = s;
    __syncthreads();

    if (threadIdx.x == 0) {
        float t = ws[0];
        #pragma unroll
        for (int w = 1; w < BLOCK / 32; w++) t += ws[w];

        float h = fmaxf(t - 1.0f, 0.0f);
        atomicAdd(&g_acc, h);
        __threadfence();
        unsigned done = atomicAdd(&g_count, 1u);
        if (done == (unsigned)gridDim.x - 1u) {
            float total = *(volatile float*)&g_acc;
            out[0] = total / (float)gridDim.x;
            // Reset for next graph replay.
            *(volatile float*)&g_acc = 0.0f;
            *(volatile unsigned*)&g_count = 0u;
            __threadfence();
        }
    }
}

// Specialized kernel for cols==16384: one CTA per row, 512 threads, each
// thread loads exactly 8 float4 fully unrolled (8 LDG.128 front-batched at
// immediate offsets -> MLP_p1 = 8, zero loop overhead).
__global__ void __launch_bounds__(BLOCK) bloss_unrolled_kernel(
    const float* __restrict__ B, float* __restrict__ out)
{
    const float4* __restrict__ p =
        reinterpret_cast<const float4*>(B + (size_t)blockIdx.x * COLS)
        + threadIdx.x;

    float4 v0 = __ldcs(p);
    float4 v1 = __ldcs(p + 1 * BLOCK);
    float4 v2 = __ldcs(p + 2 * BLOCK);
    float4 v3 = __ldcs(p + 3 * BLOCK);
    float4 v4 = __ldcs(p + 4 * BLOCK);
    float4 v5 = __ldcs(p + 5 * BLOCK);
    float4 v6 = __ldcs(p + 6 * BLOCK);
    float4 v7 = __ldcs(p + 7 * BLOCK);

    float s0 = (v0.x + v0.y) + (v0.z + v0.w);
    float s1 = (v1.x + v1.y) + (v1.z + v1.w);
    float s2 = (v2.x + v2.y) + (v2.z + v2.w);
    float s3 = (v3.x + v3.y) + (v3.z + v3.w);
    float s4 = (v4.x + v4.y) + (v4.z + v4.w);
    float s5 = (v5.x + v5.y) + (v5.z + v5.w);
    float s6 = (v6.x + v6.y) + (v6.z + v6.w);
    float s7 = (v7.x + v7.y) + (v7.z + v7.w);

    float s = ((s0 + s1) + (s2 + s3)) + ((s4 + s5) + (s6 + s7));
    epilogue(s, out);
}

// Generic fallback (any cols divisible by 4), same structure as R3.
__global__ void __launch_bounds__(BLOCK) bloss_generic_kernel(
    const float* __restrict__ B, float* __restrict__ out, int cols)
{
    const float4* __restrict__ p =
        reinterpret_cast<const float4*>(B + (size_t)blockIdx.x * (size_t)cols);
    const int n4 = cols >> 2;

    float s0 = 0.0f, s1 = 0.0f, s2 = 0.0f, s3 = 0.0f;
    int i = threadIdx.x;
    for (; i + 3 * BLOCK < n4; i += 4 * BLOCK) {
        float4 v0 = __ldcs(p + i);
        float4 v1 = __ldcs(p + i + BLOCK);
        float4 v2 = __ldcs(p + i + 2 * BLOCK);
        float4 v3 = __ldcs(p + i + 3 * BLOCK);
        s0 += (v0.x + v0.y) + (v0.z + v0.w);
        s1 += (v1.x + v1.y) + (v1.z + v1.w);
        s2 += (v2.x + v2.y) + (v2.z + v2.w);
        s3 += (v3.x + v3.y) + (v3.z + v3.w);
    }
    for (; i < n4; i += BLOCK) {
        float4 v = __ldcs(p + i);
        s0 += (v.x + v.y) + (v.z + v.w);
    }
    epilogue((s0 + s1) + (s2 + s3), out);
}

extern "C" void kernel_launch(void* const* d_in, const int* in_sizes, int n_in,
                              void* d_out, int out_size)
{
    const float* B = (const float*)d_in[0];
    const int rows = ROWS;                   // 8192 per problem spec
    const int cols = in_sizes[0] / rows;     // 16384

    if (cols == COLS)
        bloss_unrolled_kernel<<<rows, BLOCK>>>(B, (float*)d_out);
    else
        bloss_generic_kernel<<<rows, BLOCK>>>(B, (float*)d_out, cols);
}